// round 10
// baseline (speedup 1.0000x reference)
#include <cuda_runtime.h>
#include <cuda_bf16.h>
#include <math_constants.h>
#include <cstdint>
#include <cstddef>

// ===========================================================================
// KNN classifier (cosine sim, top-k=20 vote over 9 classes)
//   d_in[0] train_features [100000, 256] f32
//   d_in[1] train_labels   [100000]      i32
//   d_in[2] x              [2048, 256]   f32
//   d_in[3] k              scalar i32 (device)
//   out     [2048] f32 class ids
//
// sim ordering = dot(x, t*invnorm(t)); ||x|| constant per test row -> dropped.
// bf16x2 split: v = hi + lo;  x.t ~= x_hi t_hi + x_hi t_lo + x_lo t_hi
// packed into ONE bf16 GEMM with K=768:
//   A' = [x_hi | x_hi | x_lo]   (2048 x 768)
//   B' = [t_hi | t_lo | t_hi]   (100096 x 768, rows >= N zeroed)
//
// R10: cp.async pipeline removed (R8/R9 died in-container 4x on identical
// source; isolating). GEMM = R6's hardware-validated register-staged
// double-buffer structure + ldsm_x4 B fragments + fused per-row tile-max
// epilogue. theta kernel -> per-row threshold; single-pass topk + vote.
// ===========================================================================

#define NCLASS 9
#define MAXK   32

#define BM 128
#define BN 128
#define BK 32
#define KTOT 768
#define NCH (KTOT / BK)          // 24
#define APITCH 40                // bf16 row pitch (80 bytes)
#define CAP 2048

// ----- scratch (device globals: allowed no-alloc workaround) ---------------
static __device__ __align__(1024) float         g_sims[(size_t)2048 * 100000];
static __device__ __align__(1024) __nv_bfloat16 g_bp[(size_t)100096 * 768];
static __device__ __align__(1024) __nv_bfloat16 g_ap[(size_t)2048 * 768];
static __device__ __align__(1024) uint32_t      g_tmax[(size_t)2048 * 784];
static __device__ float                         g_theta[2048];

// ----- PTX helpers ---------------------------------------------------------
__device__ __forceinline__ uint32_t smem_u32(const void* p) {
    uint32_t a;
    asm("{ .reg .u64 t; cvta.to.shared.u64 t, %1; cvt.u32.u64 %0, t; }"
        : "=r"(a) : "l"(p));
    return a;
}
__device__ __forceinline__ void ldsm_x4(uint32_t& r0, uint32_t& r1,
                                        uint32_t& r2, uint32_t& r3, uint32_t addr) {
    asm volatile("ldmatrix.sync.aligned.m8n8.x4.shared.b16 {%0,%1,%2,%3}, [%4];"
                 : "=r"(r0), "=r"(r1), "=r"(r2), "=r"(r3) : "r"(addr));
}
__device__ __forceinline__ void mma_16816(float* c, const uint32_t* a, const uint32_t* b) {
    asm volatile("mma.sync.aligned.m16n8k16.row.col.f32.bf16.bf16.f32 "
                 "{%0,%1,%2,%3}, {%4,%5,%6,%7}, {%8,%9}, {%0,%1,%2,%3};"
                 : "+f"(c[0]), "+f"(c[1]), "+f"(c[2]), "+f"(c[3])
                 : "r"(a[0]), "r"(a[1]), "r"(a[2]), "r"(a[3]), "r"(b[0]), "r"(b[1]));
}

// monotonic f32 <-> u32 key (order-preserving incl. negatives)
__device__ __forceinline__ uint32_t fkey(float v) {
    uint32_t b = __float_as_uint(v);
    return (b & 0x80000000u) ? ~b : (b | 0x80000000u);
}
__device__ __forceinline__ float inv_fkey(uint32_t k) {
    uint32_t b = (k & 0x80000000u) ? (k & 0x7FFFFFFFu) : ~k;
    return __uint_as_float(b);
}

// ===========================================================================
// Phase 0a: normalize + bf16-split + pack train rows -> B' [t_hi | t_lo | t_hi]
// ===========================================================================
__global__ void pack_train_kernel(const float* __restrict__ T, int n, int npad)
{
    int row  = blockIdx.x * 8 + (threadIdx.x >> 5);
    int lane = threadIdx.x & 31;
    if (row >= npad) return;
    __nv_bfloat16* out = g_bp + (size_t)row * KTOT;
    if (row >= n) {
        for (int i = lane; i < KTOT; i += 32) out[i] = __float2bfloat16(0.0f);
        return;
    }
    const float* r = T + (size_t)row * 256;
    float4 v0 = *(const float4*)(r + lane * 4);
    float4 v1 = *(const float4*)(r + 128 + lane * 4);
    float s = v0.x*v0.x + v0.y*v0.y + v0.z*v0.z + v0.w*v0.w
            + v1.x*v1.x + v1.y*v1.y + v1.z*v1.z + v1.w*v1.w;
    #pragma unroll
    for (int o = 16; o > 0; o >>= 1) s += __shfl_xor_sync(0xffffffffu, s, o);
    float inv = rsqrtf(fmaxf(s, 1e-30f));

    float e[8] = {v0.x, v0.y, v0.z, v0.w, v1.x, v1.y, v1.z, v1.w};
    #pragma unroll
    for (int j = 0; j < 8; j++) {
        int idx = (j < 4) ? (lane * 4 + j) : (128 + lane * 4 + j - 4);
        float v = e[j] * inv;
        __nv_bfloat16 hi = __float2bfloat16(v);
        __nv_bfloat16 lo = __float2bfloat16(v - __bfloat162float(hi));
        out[idx]       = hi;
        out[256 + idx] = lo;
        out[512 + idx] = hi;
    }
}

// Phase 0b: split + pack x rows -> A' [x_hi | x_hi | x_lo]
__global__ void pack_x_kernel(const float* __restrict__ X, int m)
{
    int row  = blockIdx.x * 8 + (threadIdx.x >> 5);
    int lane = threadIdx.x & 31;
    if (row >= m) return;
    const float* r = X + (size_t)row * 256;
    __nv_bfloat16* out = g_ap + (size_t)row * KTOT;
    float4 v0 = *(const float4*)(r + lane * 4);
    float4 v1 = *(const float4*)(r + 128 + lane * 4);
    float e[8] = {v0.x, v0.y, v0.z, v0.w, v1.x, v1.y, v1.z, v1.w};
    #pragma unroll
    for (int j = 0; j < 8; j++) {
        int idx = (j < 4) ? (lane * 4 + j) : (128 + lane * 4 + j - 4);
        float v = e[j];
        __nv_bfloat16 hi = __float2bfloat16(v);
        __nv_bfloat16 lo = __float2bfloat16(v - __bfloat162float(hi));
        out[idx]       = hi;
        out[256 + idx] = hi;
        out[512 + idx] = lo;
    }
}

// ===========================================================================
// Phase 1: HMMA bf16 GEMM, R6-validated register-staged double buffer,
// ldsm_x4 B fragments, fused per-row tile-max epilogue.
// 256 threads = 8 warps, warp tile 64x32.
// ===========================================================================
__global__ __launch_bounds__(256)
void gemm_hmma_kernel(const __nv_bfloat16* __restrict__ Ain,
                      const __nv_bfloat16* __restrict__ Bin,
                      int Nn, int ntb)
{
    __shared__ __align__(16) __nv_bfloat16 As[2][BM][APITCH];
    __shared__ __align__(16) __nv_bfloat16 Bs[2][BN][APITCH];
    __shared__ uint32_t srmax[128];

    const int tid  = threadIdx.x;
    const int lane = tid & 31;
    const int w    = tid >> 5;
    const int wm   = w & 1;
    const int wn   = w >> 1;
    const int m0   = blockIdx.x * BM;
    const int n0   = blockIdx.y * BN;

    if (tid < 128) srmax[tid] = 0u;   // fkey-space minimum

    const int ldRow = tid >> 2;
    const int ldQ   = (tid & 3) * 8;
    const __nv_bfloat16* Aptr  = Ain + (size_t)(m0 + ldRow) * KTOT + ldQ;
    const __nv_bfloat16* Aptr2 = Ain + (size_t)(m0 + 64 + ldRow) * KTOT + ldQ;
    const __nv_bfloat16* Bptr  = Bin + (size_t)(n0 + ldRow) * KTOT + ldQ;
    const __nv_bfloat16* Bptr2 = Bin + (size_t)(n0 + 64 + ldRow) * KTOT + ldQ;

    float acc[4][4][4];
    #pragma unroll
    for (int i = 0; i < 4; i++)
        #pragma unroll
        for (int j = 0; j < 4; j++)
            #pragma unroll
            for (int q = 0; q < 4; q++) acc[i][j][q] = 0.f;

    // ldmatrix addresses (stage 0 base)
    // A x4: lanes 0-15 -> rows m0..15 @k0, lanes 16-31 -> rows m0..15 @k8
    const uint32_t aAddr0 = smem_u32(&As[0][wm * 64 + (lane & 15)][(lane >> 4) * 8]);
    // B x4: lanes 0-7 n0-7@k0, 8-15 n0-7@k8, 16-23 n8-15@k0, 24-31 n8-15@k8
    const uint32_t bAddr0 = smem_u32(
        &Bs[0][wn * 32 + ((lane >> 4) & 1) * 8 + (lane & 7)][((lane >> 3) & 1) * 8]);
    const uint32_t stageA = (uint32_t)(BM * APITCH * 2);
    const uint32_t stageB = (uint32_t)(BN * APITCH * 2);

    uint4 pa, pa2, pb, pb2;

    // prologue: chunk 0 into stage 0
    pa  = *(const uint4*)Aptr;   pa2 = *(const uint4*)Aptr2;
    pb  = *(const uint4*)Bptr;   pb2 = *(const uint4*)Bptr2;
    *(uint4*)&As[0][ldRow][ldQ]      = pa;
    *(uint4*)&As[0][64 + ldRow][ldQ] = pa2;
    *(uint4*)&Bs[0][ldRow][ldQ]      = pb;
    *(uint4*)&Bs[0][64 + ldRow][ldQ] = pb2;
    __syncthreads();

    for (int c = 0; c < NCH; c++) {
        const int s = c & 1;
        if (c + 1 < NCH) {
            const int koff = (c + 1) * BK;          // bf16 elements
            pa  = *(const uint4*)(Aptr  + koff);
            pa2 = *(const uint4*)(Aptr2 + koff);
            pb  = *(const uint4*)(Bptr  + koff);
            pb2 = *(const uint4*)(Bptr2 + koff);
        }

        const uint32_t aAddr = aAddr0 + s * stageA;
        const uint32_t bAddr = bAddr0 + s * stageB;
        #pragma unroll
        for (int ks = 0; ks < 2; ks++) {
            const uint32_t kOffB = ks * 32;         // 16 bf16 = 32 bytes
            uint32_t a[4][4];
            #pragma unroll
            for (int mf = 0; mf < 4; mf++)
                ldsm_x4(a[mf][0], a[mf][1], a[mf][2], a[mf][3],
                        aAddr + mf * 16 * (APITCH * 2) + kOffB);
            uint32_t b0[4], b1[4];
            ldsm_x4(b0[0], b0[1], b0[2], b0[3], bAddr + kOffB);          // nf 0,1
            ldsm_x4(b1[0], b1[1], b1[2], b1[3], bAddr + 1280 + kOffB);   // nf 2,3
            #pragma unroll
            for (int mf = 0; mf < 4; mf++) {
                mma_16816(acc[mf][0], a[mf], &b0[0]);
                mma_16816(acc[mf][1], a[mf], &b0[2]);
                mma_16816(acc[mf][2], a[mf], &b1[0]);
                mma_16816(acc[mf][3], a[mf], &b1[2]);
            }
        }

        if (c + 1 < NCH) {
            const int ns = (c + 1) & 1;
            __syncthreads();
            *(uint4*)&As[ns][ldRow][ldQ]      = pa;
            *(uint4*)&As[ns][64 + ldRow][ldQ] = pa2;
            *(uint4*)&Bs[ns][ldRow][ldQ]      = pb;
            *(uint4*)&Bs[ns][64 + ldRow][ldQ] = pb2;
            __syncthreads();
        }
    }

    // ---- epilogue: stores + fused per-row tile max ----
    const int mW = m0 + wm * 64;
    const int nW = n0 + wn * 32;
    #pragma unroll
    for (int mf = 0; mf < 4; mf++) {
        const int r0 = mW + mf * 16 + (lane >> 2);
        float v0 = -CUDART_INF_F, v1 = -CUDART_INF_F;
        #pragma unroll
        for (int nf = 0; nf < 4; nf++) {
            const int col = nW + nf * 8 + (lane & 3) * 2;
            if (col < Nn) {
                float2 s0 = make_float2(acc[mf][nf][0], acc[mf][nf][1]);
                float2 s1 = make_float2(acc[mf][nf][2], acc[mf][nf][3]);
                *(float2*)(g_sims + (size_t)r0 * Nn + col)       = s0;
                *(float2*)(g_sims + (size_t)(r0 + 8) * Nn + col) = s1;
                v0 = fmaxf(v0, fmaxf(s0.x, s0.y));
                v1 = fmaxf(v1, fmaxf(s1.x, s1.y));
            }
        }
        #pragma unroll
        for (int o = 1; o <= 2; o <<= 1) {
            v0 = fmaxf(v0, __shfl_xor_sync(0xffffffffu, v0, o));
            v1 = fmaxf(v1, __shfl_xor_sync(0xffffffffu, v1, o));
        }
        if ((lane & 3) == 0) {
            const int lr = wm * 64 + mf * 16 + (lane >> 2);
            atomicMax(&srmax[lr],     fkey(v0));
            atomicMax(&srmax[lr + 8], fkey(v1));
        }
    }
    __syncthreads();
    if (tid < 128)
        g_tmax[(size_t)(m0 + tid) * ntb + blockIdx.y] = srmax[tid];
}

// ===========================================================================
// Phase 1.5: theta[row] = k-th largest of the row's tile maxima. Warp/row.
// (theta <= true k-th row value: at most k-1 tile maxima exceed it.)
// ===========================================================================
__global__ __launch_bounds__(256)
void theta_kernel(const int* __restrict__ kptr, int ntb, int rows)
{
    __shared__ uint32_t sv[8][800];
    const int warp = threadIdx.x >> 5;
    const int lane = threadIdx.x & 31;
    const int row  = blockIdx.x * 8 + warp;
    if (row >= rows) return;
    int k = kptr ? *kptr : 20;
    if (k < 1) k = 1;
    if (k > MAXK) k = MAXK;
    if (k > ntb) k = ntb;

    const uint32_t* src = g_tmax + (size_t)row * ntb;
    for (int i = lane; i < ntb; i += 32) sv[warp][i] = src[i];
    __syncwarp();

    uint32_t kth = 0;
    for (int r = 0; r < k; r++) {
        uint32_t lv = 0; int la = -1;
        for (int i = lane; i < ntb; i += 32) {
            uint32_t v = sv[warp][i];
            if (v > lv) { lv = v; la = i; }
        }
        #pragma unroll
        for (int o = 16; o > 0; o >>= 1) {
            uint32_t ov = __shfl_down_sync(0xffffffffu, lv, o);
            int      oa = __shfl_down_sync(0xffffffffu, la, o);
            if (ov > lv) { lv = ov; la = oa; }
        }
        la  = __shfl_sync(0xffffffffu, la, 0);
        kth = __shfl_sync(0xffffffffu, lv, 0);
        if (lane == 0 && la >= 0) sv[warp][la] = 0;
        __syncwarp();
    }
    if (lane == 0) g_theta[row] = inv_fkey(kth);
}

// ===========================================================================
// Phase 2: single-pass threshold filter + compaction + warp argmax + vote.
// ===========================================================================
__global__ __launch_bounds__(256)
void topk_vote_kernel(const int* __restrict__ labels,
                      const int* __restrict__ kptr,
                      float* __restrict__ out, int N)
{
    const int m    = blockIdx.x;
    const int tid  = threadIdx.x;
    const int lane = tid & 31;
    const int warp = tid >> 5;
    int k = kptr ? *kptr : 20;
    if (k < 1) k = 1;
    if (k > MAXK) k = MAXK;

    const float* row = g_sims + (size_t)m * N;
    const float  th  = g_theta[m];

    __shared__ unsigned long long cand[CAP];
    __shared__ int scnt;
    __shared__ unsigned long long ssel[MAXK];
    if (tid == 0) scnt = 0;
    __syncthreads();

    const int nChunks = N >> 10;
    for (int c = 0; c < nChunks; c++) {
        int base = (c << 10) + (tid << 2);
        float4 v = *(const float4*)(row + base);
        #pragma unroll
        for (int q = 0; q < 4; q++) {
            float vv = (q == 0) ? v.x : (q == 1) ? v.y : (q == 2) ? v.z : v.w;
            if (vv >= th) {
                int p = atomicAdd(&scnt, 1);
                if (p < CAP)
                    cand[p] = ((unsigned long long)fkey(vv) << 32) |
                              (uint32_t)(~(uint32_t)(base + q));
            }
        }
    }
    for (int j = (nChunks << 10) + tid; j < N; j += 256) {
        float vv = row[j];
        if (vv >= th) {
            int p = atomicAdd(&scnt, 1);
            if (p < CAP)
                cand[p] = ((unsigned long long)fkey(vv) << 32) |
                          (uint32_t)(~(uint32_t)j);
        }
    }
    __syncthreads();
    const int cnt = scnt;

    if (cnt <= CAP) {
        if (warp == 0) {
            for (int r = 0; r < k; r++) {
                unsigned long long lv = 0ull; int la = -1;
                for (int s = lane; s < cnt; s += 32) {
                    unsigned long long c2 = cand[s];
                    if (c2 > lv) { lv = c2; la = s; }
                }
                #pragma unroll
                for (int o = 16; o > 0; o >>= 1) {
                    unsigned long long ov = __shfl_down_sync(0xffffffffu, lv, o);
                    int oa = __shfl_down_sync(0xffffffffu, la, o);
                    if (ov > lv) { lv = ov; la = oa; }
                }
                la = __shfl_sync(0xffffffffu, la, 0);
                lv = __shfl_sync(0xffffffffu, lv, 0);
                if (lane == 0) {
                    ssel[r] = lv;
                    if (la >= 0) cand[la] = 0ull;
                }
                __syncwarp();
            }
            if (lane == 0) {
                int counts[NCLASS];
                #pragma unroll
                for (int c = 0; c < NCLASS; c++) counts[c] = 0;
                for (int r = 0; r < k; r++) {
                    if (ssel[r] == 0ull) continue;
                    int j = (int)(~(uint32_t)(ssel[r] & 0xFFFFFFFFull));
                    int lab = labels[j];
                    if (lab >= 0 && lab < NCLASS) counts[lab]++;
                }
                int best = 0;
                #pragma unroll
                for (int c = 1; c < NCLASS; c++)
                    if (counts[c] > counts[best]) best = c;  // ties -> smallest
                out[m] = (float)best;
            }
        }
        return;
    }

    // ---- exact fallback (candidate overflow; practically never hit) ----
    {
        float tv[MAXK]; int ti[MAXK];
        int cnt2 = 0; float thr = -CUDART_INF_F;
        auto consider = [&](float v, int j) {
            if (cnt2 == k) {
                if (v <= thr) return;
                int p = k - 1;
                while (p > 0 && tv[p-1] < v) { tv[p]=tv[p-1]; ti[p]=ti[p-1]; p--; }
                tv[p] = v; ti[p] = j; thr = tv[k-1];
            } else {
                int p = cnt2++;
                while (p > 0 && tv[p-1] < v) { tv[p]=tv[p-1]; ti[p]=ti[p-1]; p--; }
                tv[p] = v; ti[p] = j;
                if (cnt2 == k) thr = tv[k-1];
            }
        };
        for (int c = 0; c < nChunks; c++) {
            int base = (c << 10) + (tid << 2);
            float4 v = *(const float4*)(row + base);
            consider(v.x, base); consider(v.y, base+1);
            consider(v.z, base+2); consider(v.w, base+3);
        }
        for (int j = (nChunks << 10) + tid; j < N; j += 256)
            consider(row[j], j);

        __shared__ float sval[256];
        __shared__ int   sarg[256];
        __shared__ int   selIdx[MAXK];
        int cur = 0;
        for (int r = 0; r < k; r++) {
            sval[tid] = (cur < cnt2) ? tv[cur] : -CUDART_INF_F;
            sarg[tid] = tid;
            __syncthreads();
            #pragma unroll
            for (int s = 128; s > 0; s >>= 1) {
                if (tid < s && sval[tid+s] > sval[tid]) {
                    sval[tid] = sval[tid+s]; sarg[tid] = sarg[tid+s];
                }
                __syncthreads();
            }
            if (tid == sarg[0]) { selIdx[r] = ti[cur]; cur++; }
            __syncthreads();
        }
        if (tid == 0) {
            int counts[NCLASS];
            #pragma unroll
            for (int c = 0; c < NCLASS; c++) counts[c] = 0;
            for (int r = 0; r < k; r++) {
                int lab = labels[selIdx[r]];
                if (lab >= 0 && lab < NCLASS) counts[lab]++;
            }
            int best = 0;
            #pragma unroll
            for (int c = 1; c < NCLASS; c++)
                if (counts[c] > counts[best]) best = c;
            out[m] = (float)best;
        }
    }
}

// ===========================================================================
// host launcher
// ===========================================================================
extern "C" void kernel_launch(void* const* d_in, const int* in_sizes, int n_in,
                              void* d_out, int out_size)
{
    const float* train  = (const float*)d_in[0];
    const int*   labels = (const int*)d_in[1];
    const float* x      = (const float*)d_in[2];
    const int*   kptr   = (n_in > 3) ? (const int*)d_in[3] : nullptr;

    const int Ntrain = in_sizes[1];                               // 100000
    const int Mtest  = out_size;                                  // 2048
    const int NPAD   = ((Ntrain + BN - 1) / BN) * BN;             // 100096
    const int NTB    = NPAD / BN;                                 // 782

    void *apPtr = nullptr, *bpPtr = nullptr;
    cudaGetSymbolAddress(&apPtr, g_ap);
    cudaGetSymbolAddress(&bpPtr, g_bp);

    // Phase 0: pack/split (warp per row)
    pack_train_kernel<<<(NPAD + 7) / 8, 256>>>(train, Ntrain, NPAD);
    pack_x_kernel<<<(Mtest + 7) / 8, 256>>>(x, Mtest);

    // Phase 1: HMMA GEMM (grid.x = m-tiles fast -> B tile L2-resident)
    {
        dim3 grid(Mtest / BM, NTB);
        gemm_hmma_kernel<<<grid, 256>>>(
            (const __nv_bfloat16*)apPtr, (const __nv_bfloat16*)bpPtr, Ntrain, NTB);
    }

    // Phase 1.5: per-row threshold from tile maxima
    theta_kernel<<<(Mtest + 7) / 8, 256>>>(kptr, NTB, Mtest);

    // Phase 2: single-pass top-k + vote
    topk_vote_kernel<<<Mtest, 256>>>(labels, kptr, (float*)d_out, Ntrain);
}

// round 11
// speedup vs baseline: 1.0384x; 1.0384x over previous
#include <cuda_runtime.h>
#include <cuda_bf16.h>
#include <math_constants.h>
#include <cstdint>
#include <cstddef>

// ===========================================================================
// KNN classifier (cosine sim, top-k=20 vote over 9 classes)
//   d_in[0] train_features [100000, 256] f32
//   d_in[1] train_labels   [100000]      i32
//   d_in[2] x              [2048, 256]   f32
//   d_in[3] k              scalar i32 (device)
//   out     [2048] f32 class ids
//
// R11 strategy: FILTER-THEN-RESCORE.
//   screen GEMM: bf16 hi-only, K=256 (3x less work than the bf16x3 split).
//     |approx - exact| <= 2*2^-9*||x|| ~= 0.072 worst-case (Cauchy-Schwarz).
//   theta = k-th largest per-row tile max (from fused GEMM epilogue).
//   filter at theta - 0.5  =>  superset of true top-k (margin >> 2*eps).
//   rescore candidates EXACTLY in fp32 (dot(x,train)*invnorm), select top-k
//   by exact value (desc) / index (asc), majority vote.
// GEMM = R6 hardware-validated structure (ldsm_x2 B, reg-staged dbl buffer).
// ===========================================================================

#define NCLASS 9
#define MAXK   32

#define BM 128
#define BN 128
#define BK 32
#define KTOT 256
#define NCH (KTOT / BK)          // 8
#define APITCH 40                // bf16 row pitch (80 bytes)
#define CAP 2048
#define DELTA 0.5f

// ----- scratch (device globals: allowed no-alloc workaround) ---------------
static __device__ __align__(1024) float         g_sims[(size_t)2048 * 100000];
static __device__ __align__(1024) __nv_bfloat16 g_bp[(size_t)100096 * KTOT];
static __device__ __align__(1024) __nv_bfloat16 g_ap[(size_t)2048 * KTOT];
static __device__ __align__(1024) uint32_t      g_tmax[(size_t)2048 * 784];
static __device__ float                         g_theta[2048];
static __device__ float                         g_invnorm[100096];

// ----- PTX helpers ---------------------------------------------------------
__device__ __forceinline__ uint32_t smem_u32(const void* p) {
    uint32_t a;
    asm("{ .reg .u64 t; cvta.to.shared.u64 t, %1; cvt.u32.u64 %0, t; }"
        : "=r"(a) : "l"(p));
    return a;
}
__device__ __forceinline__ void ldsm_x4(uint32_t& r0, uint32_t& r1,
                                        uint32_t& r2, uint32_t& r3, uint32_t addr) {
    asm volatile("ldmatrix.sync.aligned.m8n8.x4.shared.b16 {%0,%1,%2,%3}, [%4];"
                 : "=r"(r0), "=r"(r1), "=r"(r2), "=r"(r3) : "r"(addr));
}
__device__ __forceinline__ void ldsm_x2(uint32_t& r0, uint32_t& r1, uint32_t addr) {
    asm volatile("ldmatrix.sync.aligned.m8n8.x2.shared.b16 {%0,%1}, [%2];"
                 : "=r"(r0), "=r"(r1) : "r"(addr));
}
__device__ __forceinline__ void mma_16816(float* c, const uint32_t* a, const uint32_t* b) {
    asm volatile("mma.sync.aligned.m16n8k16.row.col.f32.bf16.bf16.f32 "
                 "{%0,%1,%2,%3}, {%4,%5,%6,%7}, {%8,%9}, {%0,%1,%2,%3};"
                 : "+f"(c[0]), "+f"(c[1]), "+f"(c[2]), "+f"(c[3])
                 : "r"(a[0]), "r"(a[1]), "r"(a[2]), "r"(a[3]), "r"(b[0]), "r"(b[1]));
}

// monotonic f32 <-> u32 key (order-preserving incl. negatives)
__device__ __forceinline__ uint32_t fkey(float v) {
    uint32_t b = __float_as_uint(v);
    return (b & 0x80000000u) ? ~b : (b | 0x80000000u);
}
__device__ __forceinline__ float inv_fkey(uint32_t k) {
    uint32_t b = (k & 0x80000000u) ? (k & 0x7FFFFFFFu) : ~k;
    return __uint_as_float(b);
}

// ===========================================================================
// Phase 0a: normalize + bf16(hi) pack of train rows; store invnorm.
// ===========================================================================
__global__ void pack_train_kernel(const float* __restrict__ T, int n, int npad)
{
    int row  = blockIdx.x * 8 + (threadIdx.x >> 5);
    int lane = threadIdx.x & 31;
    if (row >= npad) return;
    __nv_bfloat16* out = g_bp + (size_t)row * KTOT;
    if (row >= n) {
        for (int i = lane; i < KTOT; i += 32) out[i] = __float2bfloat16(0.0f);
        if (lane == 0) g_invnorm[row] = 0.0f;
        return;
    }
    const float* r = T + (size_t)row * 256;
    float4 v0 = *(const float4*)(r + lane * 4);
    float4 v1 = *(const float4*)(r + 128 + lane * 4);
    float s = v0.x*v0.x + v0.y*v0.y + v0.z*v0.z + v0.w*v0.w
            + v1.x*v1.x + v1.y*v1.y + v1.z*v1.z + v1.w*v1.w;
    #pragma unroll
    for (int o = 16; o > 0; o >>= 1) s += __shfl_xor_sync(0xffffffffu, s, o);
    float inv = rsqrtf(fmaxf(s, 1e-30f));
    if (lane == 0) g_invnorm[row] = inv;

    float e[8] = {v0.x, v0.y, v0.z, v0.w, v1.x, v1.y, v1.z, v1.w};
    #pragma unroll
    for (int j = 0; j < 8; j++) {
        int idx = (j < 4) ? (lane * 4 + j) : (128 + lane * 4 + j - 4);
        out[idx] = __float2bfloat16(e[j] * inv);
    }
}

// Phase 0b: bf16(hi) pack of x rows
__global__ void pack_x_kernel(const float* __restrict__ X, int m)
{
    int row  = blockIdx.x * 8 + (threadIdx.x >> 5);
    int lane = threadIdx.x & 31;
    if (row >= m) return;
    const float* r = X + (size_t)row * 256;
    __nv_bfloat16* out = g_ap + (size_t)row * KTOT;
    float4 v0 = *(const float4*)(r + lane * 4);
    float4 v1 = *(const float4*)(r + 128 + lane * 4);
    float e[8] = {v0.x, v0.y, v0.z, v0.w, v1.x, v1.y, v1.z, v1.w};
    #pragma unroll
    for (int j = 0; j < 8; j++) {
        int idx = (j < 4) ? (lane * 4 + j) : (128 + lane * 4 + j - 4);
        out[idx] = __float2bfloat16(e[j]);
    }
}

// ===========================================================================
// Phase 1: screening GEMM (K=256 bf16), R6-validated structure,
// fused per-row tile-max epilogue.
// ===========================================================================
__global__ __launch_bounds__(256)
void gemm_hmma_kernel(const __nv_bfloat16* __restrict__ Ain,
                      const __nv_bfloat16* __restrict__ Bin,
                      int Nn, int ntb)
{
    __shared__ __align__(16) __nv_bfloat16 As[2][BM][APITCH];
    __shared__ __align__(16) __nv_bfloat16 Bs[2][BN][APITCH];
    __shared__ uint32_t srmax[128];

    const int tid  = threadIdx.x;
    const int lane = tid & 31;
    const int w    = tid >> 5;
    const int wm   = w & 1;
    const int wn   = w >> 1;
    const int m0   = blockIdx.x * BM;
    const int n0   = blockIdx.y * BN;

    if (tid < 128) srmax[tid] = 0u;

    const int ldRow = tid >> 2;
    const int ldQ   = (tid & 3) * 8;
    const __nv_bfloat16* Aptr  = Ain + (size_t)(m0 + ldRow) * KTOT + ldQ;
    const __nv_bfloat16* Aptr2 = Ain + (size_t)(m0 + 64 + ldRow) * KTOT + ldQ;
    const __nv_bfloat16* Bptr  = Bin + (size_t)(n0 + ldRow) * KTOT + ldQ;
    const __nv_bfloat16* Bptr2 = Bin + (size_t)(n0 + 64 + ldRow) * KTOT + ldQ;

    float acc[4][4][4];
    #pragma unroll
    for (int i = 0; i < 4; i++)
        #pragma unroll
        for (int j = 0; j < 4; j++)
            #pragma unroll
            for (int q = 0; q < 4; q++) acc[i][j][q] = 0.f;

    const uint32_t aAddr0 = smem_u32(&As[0][wm * 64 + (lane & 15)][(lane >> 4) * 8]);
    const uint32_t bAddr0 = smem_u32(&Bs[0][wn * 32 + (lane & 7)][((lane >> 3) & 1) * 8]);
    const uint32_t stageA = (uint32_t)(BM * APITCH * 2);
    const uint32_t stageB = (uint32_t)(BN * APITCH * 2);

    uint4 pa, pa2, pb, pb2;

    pa  = *(const uint4*)Aptr;   pa2 = *(const uint4*)Aptr2;
    pb  = *(const uint4*)Bptr;   pb2 = *(const uint4*)Bptr2;
    *(uint4*)&As[0][ldRow][ldQ]      = pa;
    *(uint4*)&As[0][64 + ldRow][ldQ] = pa2;
    *(uint4*)&Bs[0][ldRow][ldQ]      = pb;
    *(uint4*)&Bs[0][64 + ldRow][ldQ] = pb2;
    __syncthreads();

    for (int c = 0; c < NCH; c++) {
        const int s = c & 1;
        if (c + 1 < NCH) {
            const int koff = (c + 1) * BK;          // bf16 elements
            pa  = *(const uint4*)(Aptr  + koff);
            pa2 = *(const uint4*)(Aptr2 + koff);
            pb  = *(const uint4*)(Bptr  + koff);
            pb2 = *(const uint4*)(Bptr2 + koff);
        }

        const uint32_t aAddr = aAddr0 + s * stageA;
        const uint32_t bAddr = bAddr0 + s * stageB;
        #pragma unroll
        for (int ks = 0; ks < 2; ks++) {
            const uint32_t kOffB = ks * 32;
            uint32_t a[4][4];
            #pragma unroll
            for (int mf = 0; mf < 4; mf++)
                ldsm_x4(a[mf][0], a[mf][1], a[mf][2], a[mf][3],
                        aAddr + mf * 16 * (APITCH * 2) + kOffB);
            #pragma unroll
            for (int nf = 0; nf < 4; nf++) {
                uint32_t b[2];
                ldsm_x2(b[0], b[1], bAddr + nf * 8 * (APITCH * 2) + kOffB);
                #pragma unroll
                for (int mf = 0; mf < 4; mf++)
                    mma_16816(acc[mf][nf], a[mf], b);
            }
        }

        if (c + 1 < NCH) {
            const int ns = (c + 1) & 1;
            __syncthreads();
            *(uint4*)&As[ns][ldRow][ldQ]      = pa;
            *(uint4*)&As[ns][64 + ldRow][ldQ] = pa2;
            *(uint4*)&Bs[ns][ldRow][ldQ]      = pb;
            *(uint4*)&Bs[ns][64 + ldRow][ldQ] = pb2;
            __syncthreads();
        }
    }

    // ---- epilogue: stores + fused per-row tile max ----
    const int mW = m0 + wm * 64;
    const int nW = n0 + wn * 32;
    #pragma unroll
    for (int mf = 0; mf < 4; mf++) {
        const int r0 = mW + mf * 16 + (lane >> 2);
        float v0 = -CUDART_INF_F, v1 = -CUDART_INF_F;
        #pragma unroll
        for (int nf = 0; nf < 4; nf++) {
            const int col = nW + nf * 8 + (lane & 3) * 2;
            if (col < Nn) {
                float2 s0 = make_float2(acc[mf][nf][0], acc[mf][nf][1]);
                float2 s1 = make_float2(acc[mf][nf][2], acc[mf][nf][3]);
                *(float2*)(g_sims + (size_t)r0 * Nn + col)       = s0;
                *(float2*)(g_sims + (size_t)(r0 + 8) * Nn + col) = s1;
                v0 = fmaxf(v0, fmaxf(s0.x, s0.y));
                v1 = fmaxf(v1, fmaxf(s1.x, s1.y));
            }
        }
        #pragma unroll
        for (int o = 1; o <= 2; o <<= 1) {
            v0 = fmaxf(v0, __shfl_xor_sync(0xffffffffu, v0, o));
            v1 = fmaxf(v1, __shfl_xor_sync(0xffffffffu, v1, o));
        }
        if ((lane & 3) == 0) {
            const int lr = wm * 64 + mf * 16 + (lane >> 2);
            atomicMax(&srmax[lr],     fkey(v0));
            atomicMax(&srmax[lr + 8], fkey(v1));
        }
    }
    __syncthreads();
    if (tid < 128)
        g_tmax[(size_t)(m0 + tid) * ntb + blockIdx.y] = srmax[tid];
}

// ===========================================================================
// Phase 1.5: theta[row] = k-th largest of the row's tile maxima. Warp/row.
// ===========================================================================
__global__ __launch_bounds__(256)
void theta_kernel(const int* __restrict__ kptr, int ntb, int rows)
{
    __shared__ uint32_t sv[8][800];
    const int warp = threadIdx.x >> 5;
    const int lane = threadIdx.x & 31;
    const int row  = blockIdx.x * 8 + warp;
    if (row >= rows) return;
    int k = kptr ? *kptr : 20;
    if (k < 1) k = 1;
    if (k > MAXK) k = MAXK;
    if (k > ntb) k = ntb;

    const uint32_t* src = g_tmax + (size_t)row * ntb;
    for (int i = lane; i < ntb; i += 32) sv[warp][i] = src[i];
    __syncwarp();

    uint32_t kth = 0;
    for (int r = 0; r < k; r++) {
        uint32_t lv = 0; int la = -1;
        for (int i = lane; i < ntb; i += 32) {
            uint32_t v = sv[warp][i];
            if (v > lv) { lv = v; la = i; }
        }
        #pragma unroll
        for (int o = 16; o > 0; o >>= 1) {
            uint32_t ov = __shfl_down_sync(0xffffffffu, lv, o);
            int      oa = __shfl_down_sync(0xffffffffu, la, o);
            if (ov > lv) { lv = ov; la = oa; }
        }
        la  = __shfl_sync(0xffffffffu, la, 0);
        kth = __shfl_sync(0xffffffffu, lv, 0);
        if (lane == 0 && la >= 0) sv[warp][la] = 0;
        __syncwarp();
    }
    if (lane == 0) g_theta[row] = inv_fkey(kth);
}

// ===========================================================================
// Phase 2: filter (theta - DELTA) -> compact indices -> EXACT fp32 rescore
// -> warp argmax top-k by exact value -> vote.
// ===========================================================================
__global__ __launch_bounds__(256)
void topk_vote_kernel(const int* __restrict__ labels,
                      const int* __restrict__ kptr,
                      const float* __restrict__ X,
                      const float* __restrict__ T,
                      float* __restrict__ out, int N)
{
    const int m    = blockIdx.x;
    const int tid  = threadIdx.x;
    const int lane = tid & 31;
    const int warp = tid >> 5;
    int k = kptr ? *kptr : 20;
    if (k < 1) k = 1;
    if (k > MAXK) k = MAXK;

    const float* row = g_sims + (size_t)m * N;
    const float  th  = g_theta[m] - DELTA;

    __shared__ float sx[256];
    __shared__ int   cidx[CAP];
    __shared__ unsigned long long cand[CAP];
    __shared__ int scnt;
    __shared__ unsigned long long ssel[MAXK];

    sx[tid] = X[(size_t)m * 256 + tid];
    if (tid == 0) scnt = 0;
    __syncthreads();

    // ---- filter pass over approx sims ----
    const int nChunks = N >> 10;
    for (int c = 0; c < nChunks; c++) {
        int base = (c << 10) + (tid << 2);
        float4 v = *(const float4*)(row + base);
        #pragma unroll
        for (int q = 0; q < 4; q++) {
            float vv = (q == 0) ? v.x : (q == 1) ? v.y : (q == 2) ? v.z : v.w;
            if (vv >= th) {
                int p = atomicAdd(&scnt, 1);
                if (p < CAP) cidx[p] = base + q;
            }
        }
    }
    for (int j = (nChunks << 10) + tid; j < N; j += 256) {
        if (row[j] >= th) {
            int p = atomicAdd(&scnt, 1);
            if (p < CAP) cidx[p] = j;
        }
    }
    __syncthreads();
    int cnt = scnt;
    if (cnt > CAP) cnt = CAP;   // overflow statistically impossible at DELTA

    // ---- exact fp32 rescore of candidates ----
    const float4* sx4 = (const float4*)sx;
    for (int i = tid; i < cnt; i += 256) {
        int j = cidx[i];
        const float4* tr = (const float4*)(T + (size_t)j * 256);
        float d0 = 0.f, d1 = 0.f, d2 = 0.f, d3 = 0.f;
        #pragma unroll 16
        for (int q = 0; q < 64; q += 4) {
            float4 a0 = sx4[q],     b0 = tr[q];
            float4 a1 = sx4[q + 1], b1 = tr[q + 1];
            float4 a2 = sx4[q + 2], b2 = tr[q + 2];
            float4 a3 = sx4[q + 3], b3 = tr[q + 3];
            d0 += a0.x*b0.x + a0.y*b0.y + a0.z*b0.z + a0.w*b0.w;
            d1 += a1.x*b1.x + a1.y*b1.y + a1.z*b1.z + a1.w*b1.w;
            d2 += a2.x*b2.x + a2.y*b2.y + a2.z*b2.z + a2.w*b2.w;
            d3 += a3.x*b3.x + a3.y*b3.y + a3.z*b3.z + a3.w*b3.w;
        }
        float val = (d0 + d1 + d2 + d3) * g_invnorm[j];
        cand[i] = ((unsigned long long)fkey(val) << 32) | (uint32_t)(~(uint32_t)j);
    }
    __syncthreads();

    // ---- warp0: k rounds of argmax over exact-keyed candidates ----
    if (warp == 0) {
        for (int r = 0; r < k; r++) {
            unsigned long long lv = 0ull; int la = -1;
            for (int s = lane; s < cnt; s += 32) {
                unsigned long long c2 = cand[s];
                if (c2 > lv) { lv = c2; la = s; }
            }
            #pragma unroll
            for (int o = 16; o > 0; o >>= 1) {
                unsigned long long ov = __shfl_down_sync(0xffffffffu, lv, o);
                int oa = __shfl_down_sync(0xffffffffu, la, o);
                if (ov > lv) { lv = ov; la = oa; }
            }
            la = __shfl_sync(0xffffffffu, la, 0);
            lv = __shfl_sync(0xffffffffu, lv, 0);
            if (lane == 0) {
                ssel[r] = lv;
                if (la >= 0) cand[la] = 0ull;
            }
            __syncwarp();
        }
        if (lane == 0) {
            int counts[NCLASS];
            #pragma unroll
            for (int c = 0; c < NCLASS; c++) counts[c] = 0;
            for (int r = 0; r < k; r++) {
                if (ssel[r] == 0ull) continue;
                int j = (int)(~(uint32_t)(ssel[r] & 0xFFFFFFFFull));
                int lab = labels[j];
                if (lab >= 0 && lab < NCLASS) counts[lab]++;
            }
            int best = 0;
            #pragma unroll
            for (int c = 1; c < NCLASS; c++)
                if (counts[c] > counts[best]) best = c;  // ties -> smallest
            out[m] = (float)best;
        }
    }
}

// ===========================================================================
// host launcher
// ===========================================================================
extern "C" void kernel_launch(void* const* d_in, const int* in_sizes, int n_in,
                              void* d_out, int out_size)
{
    const float* train  = (const float*)d_in[0];
    const int*   labels = (const int*)d_in[1];
    const float* x      = (const float*)d_in[2];
    const int*   kptr   = (n_in > 3) ? (const int*)d_in[3] : nullptr;

    const int Ntrain = in_sizes[1];                               // 100000
    const int Mtest  = out_size;                                  // 2048
    const int NPAD   = ((Ntrain + BN - 1) / BN) * BN;             // 100096
    const int NTB    = NPAD / BN;                                 // 782

    void *apPtr = nullptr, *bpPtr = nullptr;
    cudaGetSymbolAddress(&apPtr, g_ap);
    cudaGetSymbolAddress(&bpPtr, g_bp);

    // Phase 0: pack (warp per row)
    pack_train_kernel<<<(NPAD + 7) / 8, 256>>>(train, Ntrain, NPAD);
    pack_x_kernel<<<(Mtest + 7) / 8, 256>>>(x, Mtest);

    // Phase 1: screening GEMM (grid.x = m-tiles fast -> B tile L2-resident)
    {
        dim3 grid(Mtest / BM, NTB);
        gemm_hmma_kernel<<<grid, 256>>>(
            (const __nv_bfloat16*)apPtr, (const __nv_bfloat16*)bpPtr, Ntrain, NTB);
    }

    // Phase 1.5: per-row threshold from tile maxima
    theta_kernel<<<(Mtest + 7) / 8, 256>>>(kptr, NTB, Mtest);

    // Phase 2: filter + exact rescore + top-k + vote
    topk_vote_kernel<<<Mtest, 256>>>(labels, kptr, x, train,
                                     (float*)d_out, Ntrain);
}

// round 12
// speedup vs baseline: 2.8136x; 2.7095x over previous
#include <cuda_runtime.h>
#include <cuda_bf16.h>
#include <math_constants.h>
#include <cstdint>
#include <cstddef>

// ===========================================================================
// KNN classifier (cosine sim, top-k=20 vote over 9 classes)
//   d_in[0] train_features [100000, 256] f32
//   d_in[1] train_labels   [100000]      i32
//   d_in[2] x              [2048, 256]   f32
//   d_in[3] k              scalar i32 (device)
//   out     [2048] f32 class ids
//
// R12: FULLY FUSED SCREEN -- no similarity matrix is ever materialized.
//   theta_m = 3.0 * ||x_m||/16  (exact stdev of dot(x, t_hat) for random
//   unit t_hat; data is iid normal by construction).
//   Screen GEMM (bf16-hi, K=256) emits only candidate COLUMN INDICES where
//   approx >= theta (atomicAdd per-row list). ~135 candidates/row expected.
//   Vote kernel: exact fp32 rescore of candidates, u64-key top-k
//   (value desc / index asc), then EXACTNESS CERTIFICATE:
//     raw_cnt <= CAP  AND  cnt >= k  AND  kth_exact >= theta + eps
//   with eps = 0.1*sigma >= screen error bound (2*2^-9*||x|| = 0.0625*sigma).
//   Certificate holds -> top-k provably exact. Fails -> full exact fp32
//   rescan of that row (never triggers statistically; correctness airtight).
// ===========================================================================

#define NCLASS 9
#define MAXK   32

#define BM 128
#define BN 128
#define BK 32
#define KTOT 256
#define NCH (KTOT / BK)          // 8
#define APITCH 40                // bf16 row pitch (80 bytes)
#define CAP 4096                 // per-row candidate capacity

// ----- scratch (device globals: allowed no-alloc workaround) ---------------
static __device__ __align__(1024) __nv_bfloat16 g_bp[(size_t)100096 * KTOT];
static __device__ __align__(1024) __nv_bfloat16 g_ap[(size_t)2048 * KTOT];
static __device__ __align__(1024) uint32_t      g_cand[(size_t)2048 * CAP];
static __device__ int                           g_cnt[2048];
static __device__ float                         g_theta[2048];
static __device__ float                         g_invnorm[100096];

// ----- PTX helpers ---------------------------------------------------------
__device__ __forceinline__ uint32_t smem_u32(const void* p) {
    uint32_t a;
    asm("{ .reg .u64 t; cvta.to.shared.u64 t, %1; cvt.u32.u64 %0, t; }"
        : "=r"(a) : "l"(p));
    return a;
}
__device__ __forceinline__ void ldsm_x4(uint32_t& r0, uint32_t& r1,
                                        uint32_t& r2, uint32_t& r3, uint32_t addr) {
    asm volatile("ldmatrix.sync.aligned.m8n8.x4.shared.b16 {%0,%1,%2,%3}, [%4];"
                 : "=r"(r0), "=r"(r1), "=r"(r2), "=r"(r3) : "r"(addr));
}
__device__ __forceinline__ void ldsm_x2(uint32_t& r0, uint32_t& r1, uint32_t addr) {
    asm volatile("ldmatrix.sync.aligned.m8n8.x2.shared.b16 {%0,%1}, [%2];"
                 : "=r"(r0), "=r"(r1) : "r"(addr));
}
__device__ __forceinline__ void mma_16816(float* c, const uint32_t* a, const uint32_t* b) {
    asm volatile("mma.sync.aligned.m16n8k16.row.col.f32.bf16.bf16.f32 "
                 "{%0,%1,%2,%3}, {%4,%5,%6,%7}, {%8,%9}, {%0,%1,%2,%3};"
                 : "+f"(c[0]), "+f"(c[1]), "+f"(c[2]), "+f"(c[3])
                 : "r"(a[0]), "r"(a[1]), "r"(a[2]), "r"(a[3]), "r"(b[0]), "r"(b[1]));
}

// monotonic f32 -> u32 key (order-preserving incl. negatives)
__device__ __forceinline__ uint32_t fkey(float v) {
    uint32_t b = __float_as_uint(v);
    return (b & 0x80000000u) ? ~b : (b | 0x80000000u);
}
__device__ __forceinline__ float inv_fkey(uint32_t k) {
    uint32_t b = (k & 0x80000000u) ? (k & 0x7FFFFFFFu) : ~k;
    return __uint_as_float(b);
}

// ===========================================================================
// Phase 0z: zero per-row candidate counters.
// ===========================================================================
__global__ void zero_cnt_kernel(int rows)
{
    int i = blockIdx.x * 256 + threadIdx.x;
    if (i < rows) g_cnt[i] = 0;
}

// ===========================================================================
// Phase 0a: normalize + bf16 pack of train rows; store invnorm.
// ===========================================================================
__global__ void pack_train_kernel(const float* __restrict__ T, int n, int npad)
{
    int row  = blockIdx.x * 8 + (threadIdx.x >> 5);
    int lane = threadIdx.x & 31;
    if (row >= npad) return;
    __nv_bfloat16* out = g_bp + (size_t)row * KTOT;
    if (row >= n) {
        for (int i = lane; i < KTOT; i += 32) out[i] = __float2bfloat16(0.0f);
        if (lane == 0) g_invnorm[row] = 0.0f;
        return;
    }
    const float* r = T + (size_t)row * 256;
    float4 v0 = *(const float4*)(r + lane * 4);
    float4 v1 = *(const float4*)(r + 128 + lane * 4);
    float s = v0.x*v0.x + v0.y*v0.y + v0.z*v0.z + v0.w*v0.w
            + v1.x*v1.x + v1.y*v1.y + v1.z*v1.z + v1.w*v1.w;
    #pragma unroll
    for (int o = 16; o > 0; o >>= 1) s += __shfl_xor_sync(0xffffffffu, s, o);
    float inv = rsqrtf(fmaxf(s, 1e-30f));
    if (lane == 0) g_invnorm[row] = inv;

    float e[8] = {v0.x, v0.y, v0.z, v0.w, v1.x, v1.y, v1.z, v1.w};
    #pragma unroll
    for (int j = 0; j < 8; j++) {
        int idx = (j < 4) ? (lane * 4 + j) : (128 + lane * 4 + j - 4);
        out[idx] = __float2bfloat16(e[j] * inv);
    }
}

// Phase 0b: bf16 pack of x rows + per-row screen threshold theta = 3*||x||/16.
__global__ void pack_x_kernel(const float* __restrict__ X, int m)
{
    int row  = blockIdx.x * 8 + (threadIdx.x >> 5);
    int lane = threadIdx.x & 31;
    if (row >= m) return;
    const float* r = X + (size_t)row * 256;
    __nv_bfloat16* out = g_ap + (size_t)row * KTOT;
    float4 v0 = *(const float4*)(r + lane * 4);
    float4 v1 = *(const float4*)(r + 128 + lane * 4);
    float s = v0.x*v0.x + v0.y*v0.y + v0.z*v0.z + v0.w*v0.w
            + v1.x*v1.x + v1.y*v1.y + v1.z*v1.z + v1.w*v1.w;
    #pragma unroll
    for (int o = 16; o > 0; o >>= 1) s += __shfl_xor_sync(0xffffffffu, s, o);
    if (lane == 0)
        g_theta[row] = 3.0f * sqrtf(fmaxf(s, 0.0f)) * (1.0f / 16.0f);

    float e[8] = {v0.x, v0.y, v0.z, v0.w, v1.x, v1.y, v1.z, v1.w};
    #pragma unroll
    for (int j = 0; j < 8; j++) {
        int idx = (j < 4) ? (lane * 4 + j) : (128 + lane * 4 + j - 4);
        out[idx] = __float2bfloat16(e[j]);
    }
}

// ===========================================================================
// Phase 1: screening GEMM (K=256 bf16, R6/R11-validated body). Epilogue:
// emit candidate column indices where acc >= theta[row]. NO sims array.
// ===========================================================================
__global__ __launch_bounds__(256)
void gemm_screen_kernel(const __nv_bfloat16* __restrict__ Ain,
                        const __nv_bfloat16* __restrict__ Bin,
                        int Nn)
{
    __shared__ __align__(16) __nv_bfloat16 As[2][BM][APITCH];
    __shared__ __align__(16) __nv_bfloat16 Bs[2][BN][APITCH];
    __shared__ float sth[128];

    const int tid  = threadIdx.x;
    const int lane = tid & 31;
    const int w    = tid >> 5;
    const int wm   = w & 1;
    const int wn   = w >> 1;
    const int m0   = blockIdx.x * BM;
    const int n0   = blockIdx.y * BN;

    if (tid < 128) sth[tid] = g_theta[m0 + tid];

    const int ldRow = tid >> 2;
    const int ldQ   = (tid & 3) * 8;
    const __nv_bfloat16* Aptr  = Ain + (size_t)(m0 + ldRow) * KTOT + ldQ;
    const __nv_bfloat16* Aptr2 = Ain + (size_t)(m0 + 64 + ldRow) * KTOT + ldQ;
    const __nv_bfloat16* Bptr  = Bin + (size_t)(n0 + ldRow) * KTOT + ldQ;
    const __nv_bfloat16* Bptr2 = Bin + (size_t)(n0 + 64 + ldRow) * KTOT + ldQ;

    float acc[4][4][4];
    #pragma unroll
    for (int i = 0; i < 4; i++)
        #pragma unroll
        for (int j = 0; j < 4; j++)
            #pragma unroll
            for (int q = 0; q < 4; q++) acc[i][j][q] = 0.f;

    const uint32_t aAddr0 = smem_u32(&As[0][wm * 64 + (lane & 15)][(lane >> 4) * 8]);
    const uint32_t bAddr0 = smem_u32(&Bs[0][wn * 32 + (lane & 7)][((lane >> 3) & 1) * 8]);
    const uint32_t stageA = (uint32_t)(BM * APITCH * 2);
    const uint32_t stageB = (uint32_t)(BN * APITCH * 2);

    uint4 pa, pa2, pb, pb2;

    pa  = *(const uint4*)Aptr;   pa2 = *(const uint4*)Aptr2;
    pb  = *(const uint4*)Bptr;   pb2 = *(const uint4*)Bptr2;
    *(uint4*)&As[0][ldRow][ldQ]      = pa;
    *(uint4*)&As[0][64 + ldRow][ldQ] = pa2;
    *(uint4*)&Bs[0][ldRow][ldQ]      = pb;
    *(uint4*)&Bs[0][64 + ldRow][ldQ] = pb2;
    __syncthreads();

    for (int c = 0; c < NCH; c++) {
        const int s = c & 1;
        if (c + 1 < NCH) {
            const int koff = (c + 1) * BK;          // bf16 elements
            pa  = *(const uint4*)(Aptr  + koff);
            pa2 = *(const uint4*)(Aptr2 + koff);
            pb  = *(const uint4*)(Bptr  + koff);
            pb2 = *(const uint4*)(Bptr2 + koff);
        }

        const uint32_t aAddr = aAddr0 + s * stageA;
        const uint32_t bAddr = bAddr0 + s * stageB;
        #pragma unroll
        for (int ks = 0; ks < 2; ks++) {
            const uint32_t kOffB = ks * 32;
            uint32_t a[4][4];
            #pragma unroll
            for (int mf = 0; mf < 4; mf++)
                ldsm_x4(a[mf][0], a[mf][1], a[mf][2], a[mf][3],
                        aAddr + mf * 16 * (APITCH * 2) + kOffB);
            #pragma unroll
            for (int nf = 0; nf < 4; nf++) {
                uint32_t b[2];
                ldsm_x2(b[0], b[1], bAddr + nf * 8 * (APITCH * 2) + kOffB);
                #pragma unroll
                for (int mf = 0; mf < 4; mf++)
                    mma_16816(acc[mf][nf], a[mf], b);
            }
        }

        if (c + 1 < NCH) {
            const int ns = (c + 1) & 1;
            __syncthreads();
            *(uint4*)&As[ns][ldRow][ldQ]      = pa;
            *(uint4*)&As[ns][64 + ldRow][ldQ] = pa2;
            *(uint4*)&Bs[ns][ldRow][ldQ]      = pb;
            *(uint4*)&Bs[ns][64 + ldRow][ldQ] = pb2;
            __syncthreads();
        }
    }

    // ---- epilogue: emit candidate indices (approx >= theta[row]) ----
    const int nW = n0 + wn * 32;
    #pragma unroll
    for (int mf = 0; mf < 4; mf++) {
        const int lr0  = wm * 64 + mf * 16 + (lane >> 2);   // local row (0..127)
        const int row0 = m0 + lr0;
        const int row1 = row0 + 8;
        const float th0 = sth[lr0];
        const float th1 = sth[lr0 + 8];
        #pragma unroll
        for (int nf = 0; nf < 4; nf++) {
            const int col = nW + nf * 8 + (lane & 3) * 2;
            #pragma unroll
            for (int q = 0; q < 4; q++) {
                const int  cc  = col + (q & 1);
                const int  rr  = (q < 2) ? row0 : row1;
                const float th = (q < 2) ? th0 : th1;
                if (cc < Nn && acc[mf][nf][q] >= th) {
                    int p = atomicAdd(&g_cnt[rr], 1);
                    if (p < CAP) g_cand[(size_t)rr * CAP + p] = (uint32_t)cc;
                }
            }
        }
    }
}

// ===========================================================================
// Phase 2: exact fp32 rescore of candidates + top-k + certificate + vote.
// Fallback: full exact rescan of the row (statistically never; exactness
// guarantee does not depend on the screen statistics).
// ===========================================================================
__global__ __launch_bounds__(256)
void vote_kernel(const int* __restrict__ labels,
                 const int* __restrict__ kptr,
                 const float* __restrict__ X,
                 const float* __restrict__ T,
                 float* __restrict__ out, int N)
{
    const int m    = blockIdx.x;
    const int tid  = threadIdx.x;
    const int lane = tid & 31;
    const int warp = tid >> 5;
    int k = kptr ? *kptr : 20;
    if (k < 1) k = 1;
    if (k > MAXK) k = MAXK;

    __shared__ float sx[256];
    __shared__ unsigned long long skey[CAP];
    __shared__ unsigned long long ssel[MAXK];
    __shared__ int sok;

    sx[tid] = X[(size_t)m * 256 + tid];
    const int raw = g_cnt[m];
    const int cnt = (raw < CAP) ? raw : CAP;
    __syncthreads();

    const float4* sx4 = (const float4*)sx;

    // ---- exact fp32 rescore of candidates ----
    for (int i = tid; i < cnt; i += 256) {
        uint32_t j = g_cand[(size_t)m * CAP + i];
        const float4* tr = (const float4*)(T + (size_t)j * 256);
        float d0 = 0.f, d1 = 0.f, d2 = 0.f, d3 = 0.f;
        #pragma unroll 8
        for (int q = 0; q < 64; q += 4) {
            float4 a0 = sx4[q],     b0 = tr[q];
            float4 a1 = sx4[q + 1], b1 = tr[q + 1];
            float4 a2 = sx4[q + 2], b2 = tr[q + 2];
            float4 a3 = sx4[q + 3], b3 = tr[q + 3];
            d0 += a0.x*b0.x + a0.y*b0.y + a0.z*b0.z + a0.w*b0.w;
            d1 += a1.x*b1.x + a1.y*b1.y + a1.z*b1.z + a1.w*b1.w;
            d2 += a2.x*b2.x + a2.y*b2.y + a2.z*b2.z + a2.w*b2.w;
            d3 += a3.x*b3.x + a3.y*b3.y + a3.z*b3.z + a3.w*b3.w;
        }
        float val = (d0 + d1 + d2 + d3) * g_invnorm[j];
        skey[i] = ((unsigned long long)fkey(val) << 32) | (uint32_t)(~j);
    }
    if (tid == 0) sok = 0;
    __syncthreads();

    // ---- warp0: k rounds of argmax + certificate ----
    if (warp == 0) {
        for (int r = 0; r < k; r++) {
            unsigned long long lv = 0ull; int la = -1;
            for (int s = lane; s < cnt; s += 32) {
                unsigned long long c2 = skey[s];
                if (c2 > lv) { lv = c2; la = s; }
            }
            #pragma unroll
            for (int o = 16; o > 0; o >>= 1) {
                unsigned long long ov = __shfl_down_sync(0xffffffffu, lv, o);
                int oa = __shfl_down_sync(0xffffffffu, la, o);
                if (ov > lv) { lv = ov; la = oa; }
            }
            la = __shfl_sync(0xffffffffu, la, 0);
            lv = __shfl_sync(0xffffffffu, lv, 0);
            if (lane == 0) {
                ssel[r] = lv;
                if (la >= 0) skey[la] = 0ull;
            }
            __syncwarp();
        }
        if (lane == 0) {
            // certificate: theta = 3*sigma, eps = 0.1*sigma = theta/30
            // (>= screen error bound 2*2^-9*||x|| = 0.0625*sigma)
            float theta = g_theta[m];
            float kthv  = inv_fkey((uint32_t)(ssel[k - 1] >> 32));
            int ok = (raw <= CAP) && (cnt >= k) &&
                     (kthv >= theta + theta * (0.1f / 3.0f));
            sok = ok;
        }
    }
    __syncthreads();

    if (sok) {
        if (tid == 0) {
            int counts[NCLASS];
            #pragma unroll
            for (int c = 0; c < NCLASS; c++) counts[c] = 0;
            for (int r = 0; r < k; r++) {
                int j = (int)(~(uint32_t)(ssel[r] & 0xFFFFFFFFull));
                int lab = labels[j];
                if (lab >= 0 && lab < NCLASS) counts[lab]++;
            }
            int best = 0;
            #pragma unroll
            for (int c = 1; c < NCLASS; c++)
                if (counts[c] > counts[best]) best = c;  // ties -> smallest
            out[m] = (float)best;
        }
        return;
    }

    // ---- exact fallback: full rescan of the row (never triggers) ----
    {
        float tv[MAXK]; int ti[MAXK];
        int cnt2 = 0; float thr = -CUDART_INF_F;
        auto consider = [&](float v, int j) {
            if (cnt2 == k) {
                if (v <= thr) return;
                int p = k - 1;
                while (p > 0 && tv[p-1] < v) { tv[p]=tv[p-1]; ti[p]=ti[p-1]; p--; }
                tv[p] = v; ti[p] = j; thr = tv[k-1];
            } else {
                int p = cnt2++;
                while (p > 0 && tv[p-1] < v) { tv[p]=tv[p-1]; ti[p]=ti[p-1]; p--; }
                tv[p] = v; ti[p] = j;
                if (cnt2 == k) thr = tv[k-1];
            }
        };
        for (int j = tid; j < N; j += 256) {
            const float4* tr = (const float4*)(T + (size_t)j * 256);
            float d0 = 0.f, d1 = 0.f, d2 = 0.f, d3 = 0.f;
            for (int q = 0; q < 64; q += 4) {
                float4 a0 = sx4[q],     b0 = tr[q];
                float4 a1 = sx4[q + 1], b1 = tr[q + 1];
                float4 a2 = sx4[q + 2], b2 = tr[q + 2];
                float4 a3 = sx4[q + 3], b3 = tr[q + 3];
                d0 += a0.x*b0.x + a0.y*b0.y + a0.z*b0.z + a0.w*b0.w;
                d1 += a1.x*b1.x + a1.y*b1.y + a1.z*b1.z + a1.w*b1.w;
                d2 += a2.x*b2.x + a2.y*b2.y + a2.z*b2.z + a2.w*b2.w;
                d3 += a3.x*b3.x + a3.y*b3.y + a3.z*b3.z + a3.w*b3.w;
            }
            consider((d0 + d1 + d2 + d3) * g_invnorm[j], j);
        }
        __shared__ unsigned long long mkey[256];
        __shared__ int marg[256];
        __shared__ int selIdx[MAXK];
        int cur = 0;
        for (int r = 0; r < k; r++) {
            mkey[tid] = (cur < cnt2)
                ? (((unsigned long long)fkey(tv[cur]) << 32) | (uint32_t)(~(uint32_t)ti[cur]))
                : 0ull;
            marg[tid] = tid;
            __syncthreads();
            #pragma unroll
            for (int s = 128; s > 0; s >>= 1) {
                if (tid < s && mkey[tid+s] > mkey[tid]) {
                    mkey[tid] = mkey[tid+s]; marg[tid] = marg[tid+s];
                }
                __syncthreads();
            }
            if (tid == marg[0]) { selIdx[r] = ti[cur]; cur++; }
            __syncthreads();
        }
        if (tid == 0) {
            int counts[NCLASS];
            #pragma unroll
            for (int c = 0; c < NCLASS; c++) counts[c] = 0;
            for (int r = 0; r < k; r++) {
                int lab = labels[selIdx[r]];
                if (lab >= 0 && lab < NCLASS) counts[lab]++;
            }
            int best = 0;
            #pragma unroll
            for (int c = 1; c < NCLASS; c++)
                if (counts[c] > counts[best]) best = c;
            out[m] = (float)best;
        }
    }
}

// ===========================================================================
// host launcher
// ===========================================================================
extern "C" void kernel_launch(void* const* d_in, const int* in_sizes, int n_in,
                              void* d_out, int out_size)
{
    const float* train  = (const float*)d_in[0];
    const int*   labels = (const int*)d_in[1];
    const float* x      = (const float*)d_in[2];
    const int*   kptr   = (n_in > 3) ? (const int*)d_in[3] : nullptr;

    const int Ntrain = in_sizes[1];                               // 100000
    const int Mtest  = out_size;                                  // 2048
    const int NPAD   = ((Ntrain + BN - 1) / BN) * BN;             // 100096
    const int NTB    = NPAD / BN;                                 // 782

    void *apPtr = nullptr, *bpPtr = nullptr;
    cudaGetSymbolAddress(&apPtr, g_ap);
    cudaGetSymbolAddress(&bpPtr, g_bp);

    // Phase 0: zero counters + pack (warp per row)
    zero_cnt_kernel<<<(Mtest + 255) / 256, 256>>>(Mtest);
    pack_train_kernel<<<(NPAD + 7) / 8, 256>>>(train, Ntrain, NPAD);
    pack_x_kernel<<<(Mtest + 7) / 8, 256>>>(x, Mtest);

    // Phase 1: fused screening GEMM (no sims materialization)
    {
        dim3 grid(Mtest / BM, NTB);
        gemm_screen_kernel<<<grid, 256>>>(
            (const __nv_bfloat16*)apPtr, (const __nv_bfloat16*)bpPtr, Ntrain);
    }

    // Phase 2: exact rescore + certificate + top-k + vote
    vote_kernel<<<Mtest, 256>>>(labels, kptr, x, train, (float*)d_out, Ntrain);
}